// round 1
// baseline (speedup 1.0000x reference)
#include <cuda_runtime.h>
#include <math.h>

#define BSZ  4
#define SEQ  2048
#define FDIM 256
#define MROWS (BSZ*SEQ)          /* 8192 */
#define ALPHA 0.2f
#define MASK_FILL -9000000000000000.0f
#define NSPLIT 8

/* ---------------- scratch (device globals: no allocation allowed) -------- */
__device__ float     g_Wh[MROWS*FDIM];          /* 8 MB  Wh = h@W            */
__device__ float     g_f1[MROWS];
__device__ float     g_f2[MROWS];
__device__ float     g_m[MROWS];                /* per (b,j) column max      */
__device__ float     g_rden[MROWS];             /* per (b,j) 1/denominator   */
__device__ unsigned  g_pmask[MROWS*(SEQ/32)];   /* 2 MB packed mask bits     */
__device__ float     g_pm[NSPLIT][MROWS];
__device__ float     g_pd[NSPLIT][MROWS];

/* =================== kernel 1: Wh = h @ W  (8192x256x256) =============== */
__global__ void gemm_wh(const float* __restrict__ A, const float* __restrict__ B) {
    const int BM = 64, BN = 64, BK = 32;
    __shared__ float As[BK][BM + 4];   /* A^T tile, padded stride 68 */
    __shared__ float Bs[BK][BN];
    const int K = FDIM;
    int bm = blockIdx.x * BM, bn = blockIdx.y * BN;
    int tid = threadIdx.x;
    int tx = tid & 15, ty = tid >> 4;
    int ar = tid >> 3;            /* 0..31 */
    int ac = (tid & 7) * 4;       /* k offset 0..28 */
    int br = tid >> 4;            /* 0..15 */
    int bc = (tid & 15) * 4;      /* 0..60 */
    float acc[4][4] = {};

    for (int k0 = 0; k0 < K; k0 += BK) {
#pragma unroll
        for (int r = 0; r < 2; r++) {
            int row = ar + 32 * r;
            float4 v = *(const float4*)&A[(size_t)(bm + row) * K + k0 + ac];
            As[ac + 0][row] = v.x; As[ac + 1][row] = v.y;
            As[ac + 2][row] = v.z; As[ac + 3][row] = v.w;
        }
#pragma unroll
        for (int r = 0; r < 2; r++) {
            int row = br + 16 * r;
            *(float4*)&Bs[row][bc] =
                *(const float4*)&B[(size_t)(k0 + row) * FDIM + bn + bc];
        }
        __syncthreads();
#pragma unroll
        for (int kk = 0; kk < BK; kk++) {
            float4 a = *(const float4*)&As[kk][ty * 4];
            float4 b = *(const float4*)&Bs[kk][tx * 4];
            float av[4] = {a.x, a.y, a.z, a.w};
            float bv[4] = {b.x, b.y, b.z, b.w};
#pragma unroll
            for (int i = 0; i < 4; i++)
#pragma unroll
                for (int j = 0; j < 4; j++)
                    acc[i][j] += av[i] * bv[j];
        }
        __syncthreads();
    }
#pragma unroll
    for (int i = 0; i < 4; i++) {
        float4 o = make_float4(acc[i][0], acc[i][1], acc[i][2], acc[i][3]);
        *(float4*)&g_Wh[(size_t)(bm + ty * 4 + i) * FDIM + bn + tx * 4] = o;
    }
}

/* ============ kernel 2: f1 = Wh@a1, f2 = Wh@a2 (warp per row) ============ */
__global__ void f1f2_kernel(const float* __restrict__ a) {
    int row  = blockIdx.x * 8 + (threadIdx.x >> 5);
    int lane = threadIdx.x & 31;
    const float* wh = &g_Wh[(size_t)row * FDIM];
    float s1 = 0.f, s2 = 0.f;
#pragma unroll
    for (int q = 0; q < 8; q++) {
        float w = wh[lane + q * 32];
        s1 += w * __ldg(&a[lane + q * 32]);
        s2 += w * __ldg(&a[FDIM + lane + q * 32]);
    }
#pragma unroll
    for (int off = 16; off; off >>= 1) {
        s1 += __shfl_xor_sync(0xffffffffu, s1, off);
        s2 += __shfl_xor_sync(0xffffffffu, s2, off);
    }
    if (!lane) { g_f1[row] = s1; g_f2[row] = s2; }
}

/* ==== kernel 3a: per-(b,j) partial online softmax over i + mask packing == */
__global__ void stats_partial(const int* __restrict__ mask) {
    int b  = blockIdx.z;
    int j  = blockIdx.x * 128 + threadIdx.x;
    int i0 = blockIdx.y * (SEQ / NSPLIT);
    int lane = threadIdx.x & 31;
    float f2v = g_f2[b * SEQ + j];
    float m = MASK_FILL, den = 0.f;
    const int* mp = mask + ((size_t)b * SEQ + i0) * SEQ + j;
    unsigned* pw = &g_pmask[((size_t)b * SEQ + i0) * (SEQ / 32) + (j >> 5)];

    for (int it = 0; it < SEQ / NSPLIT; it++) {
        int mv = mp[(size_t)it * SEQ];
        unsigned bal = __ballot_sync(0xffffffffu, mv > 0);
        if (lane == 0) pw[(size_t)it * (SEQ / 32)] = bal;
        float e = g_f1[b * SEQ + i0 + it] + f2v;
        float v = (mv > 0) ? (e >= 0.f ? e : ALPHA * e) : MASK_FILL;
        if (v > m) { den = den * __expf(m - v) + 1.f; m = v; }
        else       { den += __expf(v - m); }
    }
    g_pm[blockIdx.y][b * SEQ + j] = m;
    g_pd[blockIdx.y][b * SEQ + j] = den;
}

/* ============ kernel 3b: combine NSPLIT partials per (b,j) =============== */
__global__ void stats_combine() {
    int idx = blockIdx.x * 256 + threadIdx.x;
    float ms[NSPLIT], ds[NSPLIT];
    float m = MASK_FILL;
#pragma unroll
    for (int s = 0; s < NSPLIT; s++) {
        ms[s] = g_pm[s][idx]; ds[s] = g_pd[s][idx];
        m = fmaxf(m, ms[s]);
    }
    float den = 0.f;
#pragma unroll
    for (int s = 0; s < NSPLIT; s++) den += ds[s] * __expf(ms[s] - m);
    g_m[idx] = m;
    g_rden[idx] = 1.f / den;
}

/* ==== kernel 4: h' = P @ Wh with P built on the fly, fused ELU epilogue == */
__global__ void attn_gemm(float* __restrict__ out) {
    const int BM = 64, BN = 64, BK = 32;
    __shared__ float    As[BK][BM + 4];   /* P^T tile */
    __shared__ float    Bs[BK][BN];       /* Wh tile  */
    __shared__ float    f1s[BM];
    __shared__ float    f2s[BK], mcs[BK], rds[BK];
    __shared__ unsigned pws[BM];

    int b  = blockIdx.z;
    int i0 = blockIdx.x * BM, o0 = blockIdx.y * BN;
    int tid = threadIdx.x, tx = tid & 15, ty = tid >> 4;
    int br = tid >> 4, bc = (tid & 15) * 4;
    int pii = tid & 63;            /* i within tile for P build */
    int pj0 = (tid >> 6) * 8;      /* this thread builds 8 jj's */
    float acc[4][4] = {};

    if (tid < BM) f1s[tid] = g_f1[b * SEQ + i0 + tid];

    for (int k0 = 0; k0 < SEQ; k0 += BK) {
        /* phase 1: stage per-column stats + packed mask word */
        if (tid < BK) {
            f2s[tid] = g_f2  [b * SEQ + k0 + tid];
            mcs[tid] = g_m   [b * SEQ + k0 + tid];
            rds[tid] = g_rden[b * SEQ + k0 + tid];
        }
        if (tid < BM)
            pws[tid] = g_pmask[((size_t)b * SEQ + i0 + tid) * (SEQ / 32) + (k0 >> 5)];
        __syncthreads();

        /* phase 2: build P^T tile + load Wh tile */
        {
            unsigned w = pws[pii];
            float f1v = f1s[pii];
#pragma unroll
            for (int q = 0; q < 8; q++) {
                int jj = pj0 + q;
                float p = 0.f;
                if ((w >> jj) & 1u) {
                    float e = f1v + f2s[jj];
                    float v = e >= 0.f ? e : ALPHA * e;
                    p = __expf(v - mcs[jj]) * rds[jj];
                }
                As[jj][pii] = p;
            }
#pragma unroll
            for (int r = 0; r < 2; r++) {
                int row = br + 16 * r;
                *(float4*)&Bs[row][bc] =
                    *(const float4*)&g_Wh[((size_t)b * SEQ + k0 + row) * FDIM + o0 + bc];
            }
        }
        __syncthreads();

        /* phase 3: 4x4 outer-product FMA */
#pragma unroll
        for (int kk = 0; kk < BK; kk++) {
            float4 a = *(const float4*)&As[kk][ty * 4];
            float4 v = *(const float4*)&Bs[kk][tx * 4];
            float av[4] = {a.x, a.y, a.z, a.w};
            float bv[4] = {v.x, v.y, v.z, v.w};
#pragma unroll
            for (int i = 0; i < 4; i++)
#pragma unroll
                for (int j = 0; j < 4; j++)
                    acc[i][j] += av[i] * bv[j];
        }
        /* no sync needed here: next phase-1 writes disjoint arrays, and the
           phase-1 sync orders everyone before As/Bs are overwritten        */
        __syncthreads();
    }

    /* epilogue: ELU */
#pragma unroll
    for (int i = 0; i < 4; i++) {
        int gi = i0 + ty * 4 + i;
        float4 o;
        float x;
        x = acc[i][0]; o.x = x > 0.f ? x : __expf(x) - 1.f;
        x = acc[i][1]; o.y = x > 0.f ? x : __expf(x) - 1.f;
        x = acc[i][2]; o.z = x > 0.f ? x : __expf(x) - 1.f;
        x = acc[i][3]; o.w = x > 0.f ? x : __expf(x) - 1.f;
        *(float4*)&out[((size_t)b * SEQ + gi) * FDIM + o0 + tx * 4] = o;
    }
}

/* ============================== launcher ================================= */
extern "C" void kernel_launch(void* const* d_in, const int* in_sizes, int n_in,
                              void* d_out, int out_size) {
    const float* h = nullptr; const int* mask = nullptr;
    const float* W = nullptr; const float* a = nullptr;
    for (int t = 0; t < n_in; t++) {
        if      (in_sizes[t] == BSZ * SEQ * FDIM) h    = (const float*)d_in[t];
        else if (in_sizes[t] == BSZ * SEQ * SEQ)  mask = (const int*)  d_in[t];
        else if (in_sizes[t] == FDIM * FDIM)      W    = (const float*)d_in[t];
        else if (in_sizes[t] == 2 * FDIM)         a    = (const float*)d_in[t];
    }
    float* out = (float*)d_out;

    dim3 g1(MROWS / 64, FDIM / 64);
    gemm_wh<<<g1, 256>>>(h, W);

    f1f2_kernel<<<MROWS / 8, 256>>>(a);

    dim3 g3(SEQ / 128, NSPLIT, BSZ);
    stats_partial<<<g3, 128>>>(mask);

    stats_combine<<<MROWS / 256, 256>>>();

    dim3 g4(SEQ / 64, FDIM / 64, BSZ);
    attn_gemm<<<g4, 256>>>(out);
}

// round 3
// speedup vs baseline: 2.1368x; 2.1368x over previous
#include <cuda_runtime.h>
#include <cuda_fp16.h>
#include <cstdint>
#include <math.h>

#define BSZ  4
#define SEQ  2048
#define FDIM 256
#define MROWS (BSZ*SEQ)          /* 8192 */
#define ALPHA 0.2f
#define MASK_FILL -9000000000000000.0f
#define NSPLIT 8
#define PMW (SEQ/32)             /* 64 mask words per row */

/* ---------------- scratch (device globals: no allocation allowed) -------- */
__device__ float    g_WhT[BSZ*FDIM*SEQ];     /* 8 MB  Wh^T fp32 [b][o][tok] */
__device__ __half   g_WhH[BSZ*FDIM*SEQ];     /* 4 MB  Wh^T fp16 [b][o][tok] */
__device__ float    g_f1[MROWS];
__device__ float    g_f2[MROWS];
__device__ float2   g_f2c[MROWS];            /* {f2_j, C_j = m_j + log den_j} */
__device__ unsigned g_pmask[MROWS*PMW];      /* 2 MB packed mask bits       */
__device__ float    g_pm[NSPLIT][MROWS];
__device__ float    g_pd[NSPLIT][MROWS];

/* ======================= helpers ======================================== */
__device__ __forceinline__ uint32_t smem_u32(const void* p) {
    uint32_t a;
    asm("{ .reg .u64 t; cvta.to.shared.u64 t, %1; cvt.u32.u64 %0, t; }"
        : "=r"(a) : "l"(p));
    return a;
}
#define STS128(a, r0, r1, r2, r3) \
    asm volatile("st.shared.v4.b32 [%0], {%1,%2,%3,%4};" \
                 :: "r"(a), "r"(r0), "r"(r1), "r"(r2), "r"(r3) : "memory")
__device__ __forceinline__ uint32_t lds32(uint32_t a) {
    uint32_t v;
    asm volatile("ld.shared.b32 %0, [%1];" : "=r"(v) : "r"(a));
    return v;
}
__device__ __forceinline__ void lds128(uint32_t a, uint32_t* r) {
    asm volatile("ld.shared.v4.b32 {%0,%1,%2,%3}, [%4];"
                 : "=r"(r[0]), "=r"(r[1]), "=r"(r[2]), "=r"(r[3]) : "r"(a));
}
__device__ __forceinline__ void mma16816(float* c, uint32_t a0, uint32_t a1,
                                         uint32_t a2, uint32_t a3,
                                         uint32_t b0, uint32_t b1) {
    asm volatile("mma.sync.aligned.m16n8k16.row.col.f32.f16.f16.f32 "
                 "{%0,%1,%2,%3},{%4,%5,%6,%7},{%8,%9},{%0,%1,%2,%3};"
                 : "+f"(c[0]), "+f"(c[1]), "+f"(c[2]), "+f"(c[3])
                 : "r"(a0), "r"(a1), "r"(a2), "r"(a3), "r"(b0), "r"(b1));
}
__device__ __forceinline__ uint32_t h2u(__half2 h) { return *(uint32_t*)&h; }

/* =================== kernel 1: Wh^T (fp32 + fp16) ======================== */
__global__ void gemm_wh(const float* __restrict__ A, const float* __restrict__ B) {
    const int BM = 64, BN = 64, BK = 32;
    __shared__ float As[BK][BM + 4];
    __shared__ float Bs[BK][BN];
    __shared__ float Ts[64][68];
    const int K = FDIM;
    int bm = blockIdx.x * BM, bn = blockIdx.y * BN;
    int tid = threadIdx.x;
    int tx = tid & 15, ty = tid >> 4;
    int ar = tid >> 3, ac = (tid & 7) * 4;
    int br = tid >> 4, bc = (tid & 15) * 4;
    float acc[4][4] = {};

    for (int k0 = 0; k0 < K; k0 += BK) {
#pragma unroll
        for (int r = 0; r < 2; r++) {
            int row = ar + 32 * r;
            float4 v = *(const float4*)&A[(size_t)(bm + row) * K + k0 + ac];
            As[ac + 0][row] = v.x; As[ac + 1][row] = v.y;
            As[ac + 2][row] = v.z; As[ac + 3][row] = v.w;
        }
#pragma unroll
        for (int r = 0; r < 2; r++) {
            int row = br + 16 * r;
            *(float4*)&Bs[row][bc] =
                *(const float4*)&B[(size_t)(k0 + row) * FDIM + bn + bc];
        }
        __syncthreads();
#pragma unroll
        for (int kk = 0; kk < BK; kk++) {
            float4 a = *(const float4*)&As[kk][ty * 4];
            float4 b = *(const float4*)&Bs[kk][tx * 4];
            float av[4] = {a.x, a.y, a.z, a.w};
            float bv[4] = {b.x, b.y, b.z, b.w};
#pragma unroll
            for (int i = 0; i < 4; i++)
#pragma unroll
                for (int j = 0; j < 4; j++)
                    acc[i][j] += av[i] * bv[j];
        }
        __syncthreads();
    }
#pragma unroll
    for (int i = 0; i < 4; i++)
#pragma unroll
        for (int j = 0; j < 4; j++)
            Ts[tx * 4 + j][ty * 4 + i] = acc[i][j];
    __syncthreads();
    int b = bm / SEQ, n0 = bm % SEQ;
    int orow = tid >> 2, cs = (tid & 3) * 16;
#pragma unroll
    for (int q = 0; q < 4; q++) {
        float4 v = *(float4*)&Ts[orow][cs + 4 * q];
        size_t off = ((size_t)b * FDIM + bn + orow) * SEQ + n0 + cs + 4 * q;
        *(float4*)&g_WhT[off] = v;
        __half2 u0 = __floats2half2_rn(v.x, v.y);
        __half2 u1 = __floats2half2_rn(v.z, v.w);
        uint2 pk; pk.x = h2u(u0); pk.y = h2u(u1);
        *(uint2*)&g_WhH[off] = pk;
    }
}

/* ============ kernel 2: f1 = Wh@a1, f2 = Wh@a2 (thread per token) ======== */
__global__ void f1f2_kernel(const float* __restrict__ a) {
    int b = blockIdx.y;
    int tok = blockIdx.x * 256 + threadIdx.x;
    float s1 = 0.f, s2 = 0.f;
    const float* wt = &g_WhT[(size_t)b * FDIM * SEQ + tok];
#pragma unroll 8
    for (int o = 0; o < FDIM; o++) {
        float w = wt[(size_t)o * SEQ];
        s1 += w * __ldg(&a[o]);
        s2 += w * __ldg(&a[FDIM + o]);
    }
    g_f1[b * SEQ + tok] = s1;
    g_f2[b * SEQ + tok] = s2;
}

/* ==== kernel 3a: per-(b,j) partial online softmax over i + mask packing == */
__global__ void stats_partial(const int* __restrict__ mask) {
    int b  = blockIdx.z;
    int j  = blockIdx.x * 128 + threadIdx.x;
    int i0 = blockIdx.y * (SEQ / NSPLIT);
    int lane = threadIdx.x & 31;
    float f2v = g_f2[b * SEQ + j];
    float m = MASK_FILL, den = 0.f;
    const int* mp = mask + ((size_t)b * SEQ + i0) * SEQ + j;
    unsigned* pw = &g_pmask[((size_t)b * SEQ + i0) * PMW + (j >> 5)];

    for (int it = 0; it < SEQ / NSPLIT; it++) {
        int mv = mp[(size_t)it * SEQ];
        unsigned bal = __ballot_sync(0xffffffffu, mv > 0);
        if (lane == 0) pw[(size_t)it * PMW] = bal;
        float e = g_f1[b * SEQ + i0 + it] + f2v;
        float v = (mv > 0) ? (e >= 0.f ? e : ALPHA * e) : MASK_FILL;
        if (v > m) { den = den * __expf(m - v) + 1.f; m = v; }
        else       { den += __expf(v - m); }
    }
    g_pm[blockIdx.y][b * SEQ + j] = m;
    g_pd[blockIdx.y][b * SEQ + j] = den;
}

/* ============ kernel 3b: combine partials -> {f2, C} float2 ============== */
__global__ void stats_combine() {
    int idx = blockIdx.x * 256 + threadIdx.x;
    float ms[NSPLIT], ds[NSPLIT];
    float m = MASK_FILL;
#pragma unroll
    for (int s = 0; s < NSPLIT; s++) {
        ms[s] = g_pm[s][idx]; ds[s] = g_pd[s][idx];
        m = fmaxf(m, ms[s]);
    }
    float den = 0.f;
#pragma unroll
    for (int s = 0; s < NSPLIT; s++) den += ds[s] * __expf(ms[s] - m);
    g_f2c[idx] = make_float2(g_f2[idx], m + __logf(den));
}

/* ======= kernel 4: h' = P @ Wh via mma.sync fp16, fused P-build + ELU ==== */
/* dyn smem layout (bytes) */
#define SM_F2C   512                       /* 2048 float2 = 16 KB        */
#define SM_PS    17408                     /* 2 x 8 KB  A frag-permuted  */
#define SM_WHS   (SM_PS + 16384)           /* 2 x 10240  B [n][k pad 40] */
#define ATTN_SMEM (SM_WHS + 20480)         /* 54272 bytes                */

__global__ void __launch_bounds__(256, 1) attn_mma(float* __restrict__ out) {
    extern __shared__ char smem[];
    uint32_t sb = smem_u32(smem);
    float*  f1s = (float*)smem;
    float2* f2c = (float2*)(smem + SM_F2C);

    int tid = threadIdx.x, lane = tid & 31, wid = tid >> 5;
    int b = blockIdx.z, i0 = blockIdx.x * 128, o0 = blockIdx.y * 128;

    for (int q = tid; q < SEQ; q += 256) f2c[q] = g_f2c[b * SEQ + q];
    if (tid < 128) f1s[tid] = g_f1[b * SEQ + i0 + tid];
    __syncthreads();

    /* builder role: thread -> (mt_g, bg, bt); builds rows r0, r0+8 */
    int mt_g = tid >> 5, bg = (tid >> 2) & 7, bt = tid & 3;
    int r0 = mt_g * 16 + bg;
    const unsigned* pm0 = &g_pmask[((size_t)(b * SEQ) + i0 + r0) * PMW];
    const unsigned* pm1 = pm0 + 8 * PMW;
    float f1a = f1s[r0], f1b = f1s[r0 + 8];

    /* B loader role */
    int lr = tid >> 1, lh = tid & 1;
    const int4* wsrc =
        (const int4*)(g_WhH + ((size_t)(b * FDIM) + o0 + lr) * SEQ) + lh * 2;

    /* mma role */
    int wm = wid >> 2, wn = wid & 3, fg = lane >> 2, ft = lane & 3;
    float acc[4][4][4];
#pragma unroll
    for (int i = 0; i < 4; i++)
#pragma unroll
        for (int j = 0; j < 4; j++)
#pragma unroll
            for (int k = 0; k < 4; k++) acc[i][j][k] = 0.f;

    for (int s = 0; s < 64; s++) {
        int buf = s & 1, k0 = s * 32;
        uint32_t psb = sb + SM_PS  + (uint32_t)buf * 8192u;
        uint32_t whb = sb + SM_WHS + (uint32_t)buf * 10240u;

        /* fetch gmem early */
        int4 v0 = __ldg(wsrc + s * 4);
        int4 v1 = __ldg(wsrc + s * 4 + 1);
        unsigned w0 = __ldg(pm0 + s), w1 = __ldg(pm1 + s);

        /* build P tile directly in frag-permuted layout */
#pragma unroll
        for (int ks = 0; ks < 2; ks++) {
            int jb = k0 + ks * 16;
            float4 F0 = *(const float4*)&f2c[jb + 2 * bt];       /* f2,C x2 */
            float4 F1 = *(const float4*)&f2c[jb + 2 * bt + 8];
            int sh = ks * 16;
            float e, v;
            e = f1a + F0.x; v = e >= 0.f ? e : ALPHA * e;
            float pa0 = ((w0 >> (sh + 2*bt))     & 1u) ? __expf(v - F0.y) : 0.f;
            e = f1a + F0.z; v = e >= 0.f ? e : ALPHA * e;
            float pa1 = ((w0 >> (sh + 2*bt + 1)) & 1u) ? __expf(v - F0.w) : 0.f;
            e = f1b + F0.x; v = e >= 0.f ? e : ALPHA * e;
            float pb0 = ((w1 >> (sh + 2*bt))     & 1u) ? __expf(v - F0.y) : 0.f;
            e = f1b + F0.z; v = e >= 0.f ? e : ALPHA * e;
            float pb1 = ((w1 >> (sh + 2*bt + 1)) & 1u) ? __expf(v - F0.w) : 0.f;
            e = f1a + F1.x; v = e >= 0.f ? e : ALPHA * e;
            float pa2 = ((w0 >> (sh + 2*bt + 8)) & 1u) ? __expf(v - F1.y) : 0.f;
            e = f1a + F1.z; v = e >= 0.f ? e : ALPHA * e;
            float pa3 = ((w0 >> (sh + 2*bt + 9)) & 1u) ? __expf(v - F1.w) : 0.f;
            e = f1b + F1.x; v = e >= 0.f ? e : ALPHA * e;
            float pb2 = ((w1 >> (sh + 2*bt + 8)) & 1u) ? __expf(v - F1.y) : 0.f;
            e = f1b + F1.z; v = e >= 0.f ? e : ALPHA * e;
            float pb3 = ((w1 >> (sh + 2*bt + 9)) & 1u) ? __expf(v - F1.w) : 0.f;

            uint32_t h0 = h2u(__floats2half2_rn(pa0, pa1));  /* a0: row g   */
            uint32_t h1 = h2u(__floats2half2_rn(pb0, pb1));  /* a1: row g+8 */
            uint32_t h2_ = h2u(__floats2half2_rn(pa2, pa3)); /* a2          */
            uint32_t h3 = h2u(__floats2half2_rn(pb2, pb3));  /* a3          */
            uint32_t set = (uint32_t)(mt_g * 64 + bg * 8 + bt * 2 + ks);
            STS128(psb + ((set * 16u) ^ ((uint32_t)bg << 4)), h0, h1, h2_, h3);
        }
        /* stage B tile [n][k], rows padded to 40 halfs */
        {
            char* wd = smem + SM_WHS + buf * 10240 + lr * 80 + lh * 32;
            *(int4*)wd = v0;
            *(int4*)(wd + 16) = v1;
        }
        __syncthreads();

        /* mma phase */
#pragma unroll
        for (int ks = 0; ks < 2; ks++) {
            uint32_t afr[4][4];
#pragma unroll
            for (int mt = 0; mt < 4; mt++) {
                uint32_t set = (uint32_t)((wm * 4 + mt) * 64 + fg * 8 + ft * 2 + ks);
                lds128(psb + ((set * 16u) ^ ((uint32_t)fg << 4)), afr[mt]);
            }
#pragma unroll
            for (int nt = 0; nt < 4; nt++) {
                uint32_t bad = whb +
                    (uint32_t)((wn * 32 + nt * 8 + fg) * 80 + (ks * 16 + 2 * ft) * 2);
                uint32_t b0 = lds32(bad), b1 = lds32(bad + 16);
#pragma unroll
                for (int mt = 0; mt < 4; mt++)
                    mma16816(acc[mt][nt], afr[mt][0], afr[mt][1], afr[mt][2],
                             afr[mt][3], b0, b1);
            }
        }
    }

    /* epilogue: ELU + store */
#pragma unroll
    for (int mt = 0; mt < 4; mt++) {
        int ia = i0 + wm * 64 + mt * 16 + fg;
#pragma unroll
        for (int nt = 0; nt < 4; nt++) {
            int oc = o0 + wn * 32 + nt * 8 + 2 * ft;
            float* c = acc[mt][nt];
            float2 u; float x;
            x = c[0]; u.x = x > 0.f ? x : __expf(x) - 1.f;
            x = c[1]; u.y = x > 0.f ? x : __expf(x) - 1.f;
            *(float2*)&out[((size_t)(b * SEQ) + ia) * FDIM + oc] = u;
            x = c[2]; u.x = x > 0.f ? x : __expf(x) - 1.f;
            x = c[3]; u.y = x > 0.f ? x : __expf(x) - 1.f;
            *(float2*)&out[((size_t)(b * SEQ) + ia + 8) * FDIM + oc] = u;
        }
    }
}

/* ============================== launcher ================================= */
extern "C" void kernel_launch(void* const* d_in, const int* in_sizes, int n_in,
                              void* d_out, int out_size) {
    const float* h = nullptr; const int* mask = nullptr;
    const float* W = nullptr; const float* a = nullptr;
    for (int t = 0; t < n_in; t++) {
        if      (in_sizes[t] == BSZ * SEQ * FDIM) h    = (const float*)d_in[t];
        else if (in_sizes[t] == BSZ * SEQ * SEQ)  mask = (const int*)  d_in[t];
        else if (in_sizes[t] == FDIM * FDIM)      W    = (const float*)d_in[t];
        else if (in_sizes[t] == 2 * FDIM)         a    = (const float*)d_in[t];
    }
    float* out = (float*)d_out;

    dim3 g1(MROWS / 64, FDIM / 64);
    gemm_wh<<<g1, 256>>>(h, W);

    dim3 g2(SEQ / 256, BSZ);
    f1f2_kernel<<<g2, 256>>>(a);

    dim3 g3(SEQ / 128, NSPLIT, BSZ);
    stats_partial<<<g3, 128>>>(mask);

    stats_combine<<<MROWS / 256, 256>>>();

    cudaFuncSetAttribute(attn_mma,
                         cudaFuncAttributeMaxDynamicSharedMemorySize, ATTN_SMEM);
    dim3 g4(SEQ / 128, FDIM / 128, BSZ);
    attn_mma<<<g4, 256, ATTN_SMEM>>>(out);
}